// round 12
// baseline (speedup 1.0000x reference)
#include <cuda_runtime.h>

// LocalityEntropyLoss: feat_map [T=256, F=401408] f32
// L1 = mean over rows of entropy(softmax(row)); L2 = -entropy(softmax(mean over rows))
// Inputs ~N(0,1): no max-subtraction needed. entropy = ln S - U/S, S=sum e^x, U=sum x e^x.
//
// Single fused pass. Block = 128 threads x float4 -> owns 512 contiguous columns
// across ALL rows (784 blocks, ~6 resident/SM for tail backfill).
// 4-row joint warp reduction: 3 SHFL per row for both (S,U); full per-warp row sums.
// Column sums complete in-block -> avg-entropy contribution computed locally.
// Last block (atomic ticket) writes both outputs.

#define T_ROWS 256
#define F_COLS 401408
#define THREADS 128
#define VEC 4
#define CPB (THREADS * VEC)          // 512 columns per block
#define NBLK (F_COLS / CPB)          // 784 blocks
#define NWARP (THREADS / 32)         // 4
#define UNROLL 8

__device__ float g_rowS[T_ROWS];
__device__ float g_rowU[T_ROWS];
__device__ float g_aS;
__device__ float g_aU;
__device__ unsigned int g_done;

__global__ void init_kernel() {
    int t = threadIdx.x;
    if (t < T_ROWS) { g_rowS[t] = 0.0f; g_rowU[t] = 0.0f; }
    if (t == 0) { g_aS = 0.0f; g_aU = 0.0f; g_done = 0u; }
}

__global__ __launch_bounds__(THREADS, 6) void main_pass(const float* __restrict__ x,
                                                        float* __restrict__ out) {
    __shared__ float shS[NWARP][T_ROWS];   // 4 KB, full per-warp row sums
    __shared__ float shU[NWARP][T_ROWS];   // 4 KB
    __shared__ float shA[2 * NWARP];
    __shared__ bool  isLast;

    const int tid  = threadIdx.x;
    const int wid  = tid >> 5;
    const int lane = tid & 31;
    const int colBase = blockIdx.x * CPB + tid * VEC;
    const float4* p = (const float4*)(x + colBase);
    const int stride4 = F_COLS / 4;

    const unsigned selH = lane & 16;
    const unsigned selQ = lane & 8;
    const int qi = lane >> 3;
    const int row_off = ((qi & 1) << 1) | (qi >> 1);   // quarter -> row {0,2,1,3}
    const bool qrep = ((lane & 7) == 0);

    float c0 = 0.f, c1 = 0.f, c2 = 0.f, c3 = 0.f;

    // per-row (s,u) from this thread's 4 elements
#define ROW_SU(v, sdst, udst)                                                   \
    float sdst, udst;                                                           \
    {                                                                           \
        c0 += (v).x; c1 += (v).y; c2 += (v).z; c3 += (v).w;                     \
        float e0 = __expf((v).x), e1 = __expf((v).y);                           \
        float e2 = __expf((v).z), e3 = __expf((v).w);                           \
        sdst = (e0 + e1) + (e2 + e3);                                           \
        udst = fmaf((v).x, e0, fmaf((v).y, e1, fmaf((v).z, e2, (v).w * e3)));   \
    }

    // fold 4 rows jointly: 12 SHFL total for (s,u) of 4 rows
#define FOLD4(s0, s1, s2, s3, u0, u1, u2, u3, rbase)                          \
    do {                                                                      \
        float sA = selH ? (s1) : (s0), tA = selH ? (s0) : (s1);               \
        sA += __shfl_xor_sync(0xffffffffu, tA, 16);                           \
        float uA = selH ? (u1) : (u0), tuA = selH ? (u0) : (u1);              \
        uA += __shfl_xor_sync(0xffffffffu, tuA, 16);                          \
        float sB = selH ? (s3) : (s2), tB = selH ? (s2) : (s3);               \
        sB += __shfl_xor_sync(0xffffffffu, tB, 16);                           \
        float uB = selH ? (u3) : (u2), tuB = selH ? (u2) : (u3);              \
        uB += __shfl_xor_sync(0xffffffffu, tuB, 16);                          \
        float sC = selQ ? sB : sA, tC = selQ ? sA : sB;                       \
        sC += __shfl_xor_sync(0xffffffffu, tC, 8);                            \
        float uC = selQ ? uB : uA, tuC = selQ ? uA : uB;                      \
        uC += __shfl_xor_sync(0xffffffffu, tuC, 8);                           \
        sC += __shfl_xor_sync(0xffffffffu, sC, 4);                            \
        uC += __shfl_xor_sync(0xffffffffu, uC, 4);                            \
        sC += __shfl_xor_sync(0xffffffffu, sC, 2);                            \
        uC += __shfl_xor_sync(0xffffffffu, uC, 2);                            \
        sC += __shfl_xor_sync(0xffffffffu, sC, 1);                            \
        uC += __shfl_xor_sync(0xffffffffu, uC, 1);                            \
        if (qrep) { shS[wid][(rbase) + row_off] = sC;                         \
                    shU[wid][(rbase) + row_off] = uC; }                       \
    } while (0)

    for (int r = 0; r < T_ROWS; r += UNROLL) {
        float4 v[UNROLL];
#pragma unroll
        for (int k = 0; k < UNROLL; k++)
            v[k] = __ldcs(&p[(r + k) * stride4]);   // 8 independent LDG.128 in flight
        {
            ROW_SU(v[0], s0, u0); ROW_SU(v[1], s1, u1);
            ROW_SU(v[2], s2, u2); ROW_SU(v[3], s3, u3);
            FOLD4(s0, s1, s2, s3, u0, u1, u2, u3, r);
        }
        {
            ROW_SU(v[4], s0, u0); ROW_SU(v[5], s1, u1);
            ROW_SU(v[6], s2, u2); ROW_SU(v[7], s3, u3);
            FOLD4(s0, s1, s2, s3, u0, u1, u2, u3, r + 4);
        }
    }
#undef ROW_SU
#undef FOLD4

    // ---- avg-vector contribution: c0..c3 are the FINAL column sums ----
    {
        const float inv = 1.0f / 256.0f;
        float a0 = c0 * inv, a1 = c1 * inv, a2 = c2 * inv, a3 = c3 * inv;
        float e0 = __expf(a0), e1 = __expf(a1), e2 = __expf(a2), e3 = __expf(a3);
        float s = (e0 + e1) + (e2 + e3);
        float u = fmaf(a0, e0, fmaf(a1, e1, fmaf(a2, e2, a3 * e3)));
#pragma unroll
        for (int o = 16; o > 0; o >>= 1) {
            s += __shfl_xor_sync(0xffffffffu, s, o);
            u += __shfl_xor_sync(0xffffffffu, u, o);
        }
        if (lane == 0) { shA[wid] = s; shA[NWARP + wid] = u; }
    }

    __syncthreads();

    // Fold the 4 warp row-sums; 2 global atomics per row per block.
    for (int rr = tid; rr < T_ROWS; rr += THREADS) {
        float s = 0.f, u = 0.f;
#pragma unroll
        for (int w = 0; w < NWARP; w++) { s += shS[w][rr]; u += shU[w][rr]; }
        atomicAdd(&g_rowS[rr], s);
        atomicAdd(&g_rowU[rr], u);
    }
    if (tid == 0) {
        float s = 0.f, u = 0.f;
#pragma unroll
        for (int w = 0; w < NWARP; w++) { s += shA[w]; u += shA[NWARP + w]; }
        atomicAdd(&g_aS, s);
        atomicAdd(&g_aU, u);
    }

    // ---- last block finalizes ----
    __threadfence();
    __syncthreads();
    if (tid == 0)
        isLast = (atomicAdd(&g_done, 1u) == (unsigned)(NBLK - 1));
    __syncthreads();

    if (isLast) {
        float ent = 0.f;
#pragma unroll
        for (int k = 0; k < 2; k++) {
            int rr = tid + k * THREADS;
            float S = g_rowS[rr];
            float U = g_rowU[rr];
            ent += __logf(S) - U / S;
        }
#pragma unroll
        for (int o = 16; o > 0; o >>= 1)
            ent += __shfl_xor_sync(0xffffffffu, ent, o);
        if (lane == 0) shA[wid] = ent;
        __syncthreads();
        if (tid == 0) {
            float tot = 0.f;
#pragma unroll
            for (int w = 0; w < NWARP; w++) tot += shA[w];
            out[0] = tot * (1.0f / 256.0f);            // L1
            float Sa = g_aS, Ua = g_aU;
            out[1] = Ua / Sa - __logf(Sa);             // L2 = -entropy(avg)
        }
    }
}

extern "C" void kernel_launch(void* const* d_in, const int* in_sizes, int n_in,
                              void* d_out, int out_size) {
    const float* x = (const float*)d_in[0];
    float* out = (float*)d_out;
    init_kernel<<<1, 256>>>();
    main_pass<<<NBLK, THREADS>>>(x, out);
}

// round 15
// speedup vs baseline: 1.0009x; 1.0009x over previous
#include <cuda_runtime.h>

// LocalityEntropyLoss: feat_map [T=256, F=401408] f32
// L1 = mean over rows of entropy(softmax(row)); L2 = -entropy(softmax(mean over rows))
// Inputs ~N(0,1): no max-subtraction needed. entropy = ln S - U/S, S=sum e^x, U=sum x e^x.
//
// Single fused pass. Block = 128 threads x float4 -> owns 512 contiguous columns
// across ALL rows (784 blocks). Software-pipelined double buffer with peeled
// epilogue: 4 LDG.128 always in flight per warp during every compute phase.
// 4-row joint warp reduction: 3 SHFL per row for both (S,U); full per-warp row sums.
// Column sums complete in-block -> avg-entropy contribution computed locally.
// Last block (atomic ticket) writes both outputs.

#define T_ROWS 256
#define F_COLS 401408
#define THREADS 128
#define VEC 4
#define CPB (THREADS * VEC)          // 512 columns per block
#define NBLK (F_COLS / CPB)          // 784 blocks
#define NWARP (THREADS / 32)         // 4

__device__ float g_rowS[T_ROWS];
__device__ float g_rowU[T_ROWS];
__device__ float g_aS;
__device__ float g_aU;
__device__ unsigned int g_done;

__global__ void init_kernel() {
    int t = threadIdx.x;
    if (t < T_ROWS) { g_rowS[t] = 0.0f; g_rowU[t] = 0.0f; }
    if (t == 0) { g_aS = 0.0f; g_aU = 0.0f; g_done = 0u; }
}

__global__ __launch_bounds__(THREADS, 6) void main_pass(const float* __restrict__ x,
                                                        float* __restrict__ out) {
    __shared__ float shS[NWARP][T_ROWS];   // 4 KB, full per-warp row sums
    __shared__ float shU[NWARP][T_ROWS];   // 4 KB
    __shared__ float shA[2 * NWARP];
    __shared__ bool  isLast;

    const int tid  = threadIdx.x;
    const int wid  = tid >> 5;
    const int lane = tid & 31;
    const int colBase = blockIdx.x * CPB + tid * VEC;
    const float4* p = (const float4*)(x + colBase);
    const int stride4 = F_COLS / 4;

    const unsigned selH = lane & 16;
    const unsigned selQ = lane & 8;
    const int qi = lane >> 3;
    const int row_off = ((qi & 1) << 1) | (qi >> 1);   // quarter -> row {0,2,1,3}
    const bool qrep = ((lane & 7) == 0);

    float c0 = 0.f, c1 = 0.f, c2 = 0.f, c3 = 0.f;

    // per-row (s,u) from this thread's 4 elements
#define ROW_SU(v, sdst, udst)                                                   \
    float sdst, udst;                                                           \
    {                                                                           \
        c0 += (v).x; c1 += (v).y; c2 += (v).z; c3 += (v).w;                     \
        float e0 = __expf((v).x), e1 = __expf((v).y);                           \
        float e2 = __expf((v).z), e3 = __expf((v).w);                           \
        sdst = (e0 + e1) + (e2 + e3);                                           \
        udst = fmaf((v).x, e0, fmaf((v).y, e1, fmaf((v).z, e2, (v).w * e3)));   \
    }

    // fold 4 rows jointly: 12 SHFL total for (s,u) of 4 rows
#define FOLD4(s0, s1, s2, s3, u0, u1, u2, u3, rbase)                          \
    do {                                                                      \
        float sA = selH ? (s1) : (s0), tA = selH ? (s0) : (s1);               \
        sA += __shfl_xor_sync(0xffffffffu, tA, 16);                           \
        float uA = selH ? (u1) : (u0), tuA = selH ? (u0) : (u1);              \
        uA += __shfl_xor_sync(0xffffffffu, tuA, 16);                          \
        float sB = selH ? (s3) : (s2), tB = selH ? (s2) : (s3);               \
        sB += __shfl_xor_sync(0xffffffffu, tB, 16);                           \
        float uB = selH ? (u3) : (u2), tuB = selH ? (u2) : (u3);              \
        uB += __shfl_xor_sync(0xffffffffu, tuB, 16);                          \
        float sC = selQ ? sB : sA, tC = selQ ? sA : sB;                       \
        sC += __shfl_xor_sync(0xffffffffu, tC, 8);                            \
        float uC = selQ ? uB : uA, tuC = selQ ? uA : uB;                      \
        uC += __shfl_xor_sync(0xffffffffu, tuC, 8);                           \
        sC += __shfl_xor_sync(0xffffffffu, sC, 4);                            \
        uC += __shfl_xor_sync(0xffffffffu, uC, 4);                            \
        sC += __shfl_xor_sync(0xffffffffu, sC, 2);                            \
        uC += __shfl_xor_sync(0xffffffffu, uC, 2);                            \
        sC += __shfl_xor_sync(0xffffffffu, sC, 1);                            \
        uC += __shfl_xor_sync(0xffffffffu, uC, 1);                            \
        if (qrep) { shS[wid][(rbase) + row_off] = sC;                         \
                    shU[wid][(rbase) + row_off] = uC; }                       \
    } while (0)

#define LOAD4(dst, rbase)                                                     \
    do {                                                                      \
        _Pragma("unroll")                                                     \
        for (int k = 0; k < 4; k++)                                           \
            (dst)[k] = __ldcs(&p[((rbase) + k) * stride4]);                   \
    } while (0)

#define PROC4(v, rbase)                                                       \
    do {                                                                      \
        ROW_SU((v)[0], s0, u0); ROW_SU((v)[1], s1, u1);                       \
        ROW_SU((v)[2], s2, u2); ROW_SU((v)[3], s3, u3);                       \
        FOLD4(s0, s1, s2, s3, u0, u1, u2, u3, rbase);                         \
    } while (0)

    {
        float4 vA[4], vB[4];
        LOAD4(vA, 0);                       // prologue: rows 0..3 in flight
        // Steady state (unconditional): process half-batch r, with r+4 in flight.
        for (int r = 0; r < T_ROWS - 8; r += 8) {
            LOAD4(vB, r + 4);
            PROC4(vA, r);
            LOAD4(vA, r + 8);
            PROC4(vB, r + 4);
        }
        // Epilogue: rows 248..255 (vA holds 248..251 from the last loop iter).
        LOAD4(vB, T_ROWS - 4);
        PROC4(vA, T_ROWS - 8);
        PROC4(vB, T_ROWS - 4);
    }
#undef ROW_SU
#undef FOLD4
#undef LOAD4
#undef PROC4

    // ---- avg-vector contribution: c0..c3 are the FINAL column sums ----
    {
        const float inv = 1.0f / 256.0f;
        float a0 = c0 * inv, a1 = c1 * inv, a2 = c2 * inv, a3 = c3 * inv;
        float e0 = __expf(a0), e1 = __expf(a1), e2 = __expf(a2), e3 = __expf(a3);
        float s = (e0 + e1) + (e2 + e3);
        float u = fmaf(a0, e0, fmaf(a1, e1, fmaf(a2, e2, a3 * e3)));
#pragma unroll
        for (int o = 16; o > 0; o >>= 1) {
            s += __shfl_xor_sync(0xffffffffu, s, o);
            u += __shfl_xor_sync(0xffffffffu, u, o);
        }
        if (lane == 0) { shA[wid] = s; shA[NWARP + wid] = u; }
    }

    __syncthreads();

    // Fold the 4 warp row-sums; 2 global atomics per row per block.
    for (int rr = tid; rr < T_ROWS; rr += THREADS) {
        float s = 0.f, u = 0.f;
#pragma unroll
        for (int w = 0; w < NWARP; w++) { s += shS[w][rr]; u += shU[w][rr]; }
        atomicAdd(&g_rowS[rr], s);
        atomicAdd(&g_rowU[rr], u);
    }
    if (tid == 0) {
        float s = 0.f, u = 0.f;
#pragma unroll
        for (int w = 0; w < NWARP; w++) { s += shA[w]; u += shA[NWARP + w]; }
        atomicAdd(&g_aS, s);
        atomicAdd(&g_aU, u);
    }

    // ---- last block finalizes ----
    __threadfence();
    __syncthreads();
    if (tid == 0)
        isLast = (atomicAdd(&g_done, 1u) == (unsigned)(NBLK - 1));
    __syncthreads();

    if (isLast) {
        float ent = 0.f;
#pragma unroll
        for (int k = 0; k < 2; k++) {
            int rr = tid + k * THREADS;
            float S = g_rowS[rr];
            float U = g_rowU[rr];
            ent += __logf(S) - U / S;
        }
#pragma unroll
        for (int o = 16; o > 0; o >>= 1)
            ent += __shfl_xor_sync(0xffffffffu, ent, o);
        if (lane == 0) shA[wid] = ent;
        __syncthreads();
        if (tid == 0) {
            float tot = 0.f;
#pragma unroll
            for (int w = 0; w < NWARP; w++) tot += shA[w];
            out[0] = tot * (1.0f / 256.0f);            // L1
            float Sa = g_aS, Ua = g_aU;
            out[1] = Ua / Sa - __logf(Sa);             // L2 = -entropy(avg)
        }
    }
}

extern "C" void kernel_launch(void* const* d_in, const int* in_sizes, int n_in,
                              void* d_out, int out_size) {
    const float* x = (const float*)d_in[0];
    float* out = (float*)d_out;
    init_kernel<<<1, 256>>>();
    main_pass<<<NBLK, THREADS>>>(x, out);
}

// round 16
// speedup vs baseline: 1.0317x; 1.0308x over previous
#include <cuda_runtime.h>

// LocalityEntropyLoss: feat_map [T=256, F=401408] f32
// L1 = mean over rows of entropy(softmax(row)); L2 = -entropy(softmax(mean over rows))
// Inputs ~N(0,1): no max-subtraction needed. entropy = ln S - U/S, S=sum e^x, U=sum x e^x.
//
// SINGLE kernel launch. Block = 256 threads x float4 -> owns 1024 contiguous
// columns across ALL rows (392 blocks). 4-row joint warp reduction (3 SHFL/row
// for both S and U). Column sums complete in-block -> avg-entropy contribution
// computed locally. Last block (atomic ticket) writes outputs, then RESETS all
// global accumulators + ticket to zero so every graph replay is identical
// (device globals are zero-initialized at module load for the first run).

#define T_ROWS 256
#define F_COLS 401408
#define THREADS 256
#define VEC 4
#define CPB (THREADS * VEC)          // 1024 columns per block
#define NBLK (F_COLS / CPB)          // 392 blocks
#define NWARP (THREADS / 32)         // 8
#define UNROLL 8

__device__ float g_rowS[T_ROWS];     // zero-initialized at module load
__device__ float g_rowU[T_ROWS];
__device__ float g_aS;
__device__ float g_aU;
__device__ unsigned int g_done;

__global__ __launch_bounds__(THREADS, 3) void main_pass(const float* __restrict__ x,
                                                        float* __restrict__ out) {
    __shared__ float shS[NWARP][T_ROWS];   // 8 KB, full per-warp row sums
    __shared__ float shU[NWARP][T_ROWS];   // 8 KB
    __shared__ float shA[2 * NWARP];
    __shared__ bool  isLast;

    const int tid  = threadIdx.x;
    const int wid  = tid >> 5;
    const int lane = tid & 31;
    const int colBase = blockIdx.x * CPB + tid * VEC;
    const float4* p = (const float4*)(x + colBase);
    const int stride4 = F_COLS / 4;

    const unsigned selH = lane & 16;
    const unsigned selQ = lane & 8;
    const int qi = lane >> 3;
    const int row_off = ((qi & 1) << 1) | (qi >> 1);   // quarter -> row {0,2,1,3}
    const bool qrep = ((lane & 7) == 0);

    float c0 = 0.f, c1 = 0.f, c2 = 0.f, c3 = 0.f;

    // per-row (s,u) from this thread's 4 elements
#define ROW_SU(v, sdst, udst)                                                   \
    float sdst, udst;                                                           \
    {                                                                           \
        c0 += (v).x; c1 += (v).y; c2 += (v).z; c3 += (v).w;                     \
        float e0 = __expf((v).x), e1 = __expf((v).y);                           \
        float e2 = __expf((v).z), e3 = __expf((v).w);                           \
        sdst = (e0 + e1) + (e2 + e3);                                           \
        udst = fmaf((v).x, e0, fmaf((v).y, e1, fmaf((v).z, e2, (v).w * e3)));   \
    }

    // fold 4 rows jointly: 12 SHFL total for (s,u) of 4 rows
#define FOLD4(s0, s1, s2, s3, u0, u1, u2, u3, rbase)                          \
    do {                                                                      \
        float sA = selH ? (s1) : (s0), tA = selH ? (s0) : (s1);               \
        sA += __shfl_xor_sync(0xffffffffu, tA, 16);                           \
        float uA = selH ? (u1) : (u0), tuA = selH ? (u0) : (u1);              \
        uA += __shfl_xor_sync(0xffffffffu, tuA, 16);                          \
        float sB = selH ? (s3) : (s2), tB = selH ? (s2) : (s3);               \
        sB += __shfl_xor_sync(0xffffffffu, tB, 16);                           \
        float uB = selH ? (u3) : (u2), tuB = selH ? (u2) : (u3);              \
        uB += __shfl_xor_sync(0xffffffffu, tuB, 16);                          \
        float sC = selQ ? sB : sA, tC = selQ ? sA : sB;                       \
        sC += __shfl_xor_sync(0xffffffffu, tC, 8);                            \
        float uC = selQ ? uB : uA, tuC = selQ ? uA : uB;                      \
        uC += __shfl_xor_sync(0xffffffffu, tuC, 8);                           \
        sC += __shfl_xor_sync(0xffffffffu, sC, 4);                            \
        uC += __shfl_xor_sync(0xffffffffu, uC, 4);                            \
        sC += __shfl_xor_sync(0xffffffffu, sC, 2);                            \
        uC += __shfl_xor_sync(0xffffffffu, uC, 2);                            \
        sC += __shfl_xor_sync(0xffffffffu, sC, 1);                            \
        uC += __shfl_xor_sync(0xffffffffu, uC, 1);                            \
        if (qrep) { shS[wid][(rbase) + row_off] = sC;                         \
                    shU[wid][(rbase) + row_off] = uC; }                       \
    } while (0)

    for (int r = 0; r < T_ROWS; r += UNROLL) {
        float4 v[UNROLL];
#pragma unroll
        for (int k = 0; k < UNROLL; k++)
            v[k] = __ldcs(&p[(r + k) * stride4]);   // 8 independent LDG.128 in flight
        {
            ROW_SU(v[0], s0, u0); ROW_SU(v[1], s1, u1);
            ROW_SU(v[2], s2, u2); ROW_SU(v[3], s3, u3);
            FOLD4(s0, s1, s2, s3, u0, u1, u2, u3, r);
        }
        {
            ROW_SU(v[4], s0, u0); ROW_SU(v[5], s1, u1);
            ROW_SU(v[6], s2, u2); ROW_SU(v[7], s3, u3);
            FOLD4(s0, s1, s2, s3, u0, u1, u2, u3, r + 4);
        }
    }
#undef ROW_SU
#undef FOLD4

    // ---- avg-vector contribution: c0..c3 are the FINAL column sums ----
    {
        const float inv = 1.0f / 256.0f;
        float a0 = c0 * inv, a1 = c1 * inv, a2 = c2 * inv, a3 = c3 * inv;
        float e0 = __expf(a0), e1 = __expf(a1), e2 = __expf(a2), e3 = __expf(a3);
        float s = (e0 + e1) + (e2 + e3);
        float u = fmaf(a0, e0, fmaf(a1, e1, fmaf(a2, e2, a3 * e3)));
#pragma unroll
        for (int o = 16; o > 0; o >>= 1) {
            s += __shfl_xor_sync(0xffffffffu, s, o);
            u += __shfl_xor_sync(0xffffffffu, u, o);
        }
        if (lane == 0) { shA[wid] = s; shA[NWARP + wid] = u; }
    }

    __syncthreads();

    // Fold the 8 warp row-sums; 2 global atomics per row per block. tid == row.
    {
        float s = 0.f, u = 0.f;
#pragma unroll
        for (int w = 0; w < NWARP; w++) { s += shS[w][tid]; u += shU[w][tid]; }
        atomicAdd(&g_rowS[tid], s);
        atomicAdd(&g_rowU[tid], u);
    }
    if (tid == 0) {
        float s = 0.f, u = 0.f;
#pragma unroll
        for (int w = 0; w < NWARP; w++) { s += shA[w]; u += shA[NWARP + w]; }
        atomicAdd(&g_aS, s);
        atomicAdd(&g_aU, u);
    }

    // ---- last block finalizes, then resets globals for the next replay ----
    __threadfence();
    __syncthreads();
    if (tid == 0)
        isLast = (atomicAdd(&g_done, 1u) == (unsigned)(NBLK - 1));
    __syncthreads();

    if (isLast) {
        float S = g_rowS[tid];
        float U = g_rowU[tid];
        float ent = __logf(S) - U / S;
#pragma unroll
        for (int o = 16; o > 0; o >>= 1)
            ent += __shfl_xor_sync(0xffffffffu, ent, o);
        if (lane == 0) shA[wid] = ent;
        __syncthreads();
        if (tid == 0) {
            float tot = 0.f;
#pragma unroll
            for (int w = 0; w < NWARP; w++) tot += shA[w];
            out[0] = tot * (1.0f / 256.0f);            // L1
            float Sa = g_aS, Ua = g_aU;
            out[1] = Ua / Sa - __logf(Sa);             // L2 = -entropy(avg)
        }
        // Cleanup: zero accumulators + ticket so the next graph replay
        // starts from the exact same state (self-initializing kernel).
        g_rowS[tid] = 0.0f;
        g_rowU[tid] = 0.0f;
        if (tid == 0) { g_aS = 0.0f; g_aU = 0.0f; g_done = 0u; }
    }
}

extern "C" void kernel_launch(void* const* d_in, const int* in_sizes, int n_in,
                              void* d_out, int out_size) {
    const float* x = (const float*)d_in[0];
    float* out = (float*)d_out;
    main_pass<<<NBLK, THREADS>>>(x, out);
}